// round 10
// baseline (speedup 1.0000x reference)
#include <cuda_runtime.h>
#include <cuda_bf16.h>
#include <cstdint>

#define NN 2048
#define DD 64
#define NCTAS 296   // 148 SMs x 2 resident CTAs (persistent)

// ---------------- device scratch ----------------
__device__ float g_A[NN * DD];                       // A[i] = x_i @ W1[:64] + b1
__device__ float g_B[NN * DD];                       // B[j] = x_j @ W1[64:]
__device__ __align__(16) unsigned short g_W2Th[64 * 72];  // W2^T hi, [n][k] pitch 72
__device__ __align__(16) unsigned short g_W2Tl[64 * 72];  // W2^T lo
__device__ __align__(16) unsigned short g_W3Th[16 * 72];  // W3^T hi
__device__ __align__(16) unsigned short g_W3Tl[16 * 72];  // W3^T lo

// ---------------- helpers ----------------
__device__ __forceinline__ uint32_t smem_u32(const void* p) {
    uint32_t a;
    asm("{ .reg .u64 t; cvta.to.shared.u64 t, %1; cvt.u32.u64 %0, t; }" : "=r"(a) : "l"(p));
    return a;
}
__device__ __forceinline__ uint32_t packbf(float hi, float lo) {
    uint32_t r; asm("cvt.rn.bf16x2.f32 %0, %1, %2;" : "=r"(r) : "f"(hi), "f"(lo)); return r;
}
__device__ __forceinline__ float resid(float v) {
    return v - __uint_as_float(__float_as_uint(v) & 0xFFFF0000u);
}

#define LDSM_X4(r0, r1, r2, r3, addr) \
    asm volatile("ldmatrix.sync.aligned.m8n8.x4.shared.b16 {%0,%1,%2,%3}, [%4];" \
        : "=r"(r0), "=r"(r1), "=r"(r2), "=r"(r3) : "r"(addr))

__device__ __forceinline__ void mma_bf16(float* c, uint32_t a0, uint32_t a1,
                                         uint32_t a2, uint32_t a3,
                                         uint32_t b0, uint32_t b1) {
    asm volatile(
        "mma.sync.aligned.m16n8k16.row.col.f32.bf16.bf16.f32 "
        "{%0,%1,%2,%3}, {%4,%5,%6,%7}, {%8,%9}, {%0,%1,%2,%3};"
        : "+f"(c[0]), "+f"(c[1]), "+f"(c[2]), "+f"(c[3])
        : "r"(a0), "r"(a1), "r"(a2), "r"(a3), "r"(b0), "r"(b1));
}

// ---------------- Kernel 1: precompute A/B rows + weight tiles ----------------
__global__ void precompute_kernel(const float* __restrict__ X,
                                  const float* __restrict__ W1,
                                  const float* __restrict__ b1,
                                  const float* __restrict__ W2,
                                  const float* __restrict__ We,
                                  const float* __restrict__ Wt) {
    if (blockIdx.x < NN) {
        __shared__ float xs[DD];
        const int i = blockIdx.x;
        const int d = threadIdx.x;
        xs[d] = X[i * DD + d];
        __syncthreads();
        float a = b1[d], b = 0.f;
#pragma unroll 8
        for (int k = 0; k < DD; k++) {
            const float xv = xs[k];
            a = fmaf(xv, __ldg(&W1[k * DD + d]), a);
            b = fmaf(xv, __ldg(&W1[(DD + k) * DD + d]), b);
        }
        g_A[i * DD + d] = a;
        g_B[i * DD + d] = b;
    } else {
        const int t = threadIdx.x;
        for (int idx = t; idx < 64 * 72; idx += 64) {
            const int n = idx / 72, k = idx % 72;
            float v = (k < 64) ? W2[k * 64 + n] : 0.f;
            __nv_bfloat16 h = __float2bfloat16_rn(v);
            g_W2Th[idx] = __bfloat16_as_ushort(h);
            g_W2Tl[idx] = __bfloat16_as_ushort(__float2bfloat16_rn(v - __bfloat162float(h)));
        }
        for (int idx = t; idx < 16 * 72; idx += 64) {
            const int n = idx / 72, k = idx % 72;
            float v = 0.f;
            if (k < 64) {
                if (n == 0) v = We[k];
                else if (n < 9) v = Wt[k * 8 + n - 1];
            }
            __nv_bfloat16 h = __float2bfloat16_rn(v);
            g_W3Th[idx] = __bfloat16_as_ushort(h);
            g_W3Tl[idx] = __bfloat16_as_ushort(__float2bfloat16_rn(v - __bfloat162float(h)));
        }
    }
}

// ---------------- Kernel 2: persistent pair kernel, B cached in registers ----
// Warps: 4(M) x 2(N). Tile = 64 pairs (one i, 64 j's). Each warp caches its
// 32-col half of W2^T hi+lo as mma fragments (64 regs) ONCE; the tile loop
// does zero B-side shared-memory traffic.
__global__ __launch_bounds__(256, 2) void edge_main(
    const float* __restrict__ b2,
    const float* __restrict__ be, const float* __restrict__ bt,
    float* __restrict__ out)
{
    __shared__ __align__(16) unsigned short sBW[2 * 64 * 72];   // BH | BL
    __shared__ __align__(16) unsigned short sW3[2 * 16 * 72];   // W3 hi | lo
    __shared__ __align__(16) float sOut0[64 * 9];
    __shared__ __align__(16) float sOut1[64 * 9];
    __shared__ __align__(16) float sB2[64];
    __shared__ float sB3[16];

    const int tid  = threadIdx.x;
    const int warp = tid >> 5;
    const int lane = tid & 31;
    const int warpM = warp & 3;       // rows warpM*16 .. +16 within tile
    const int warpN = warp >> 2;      // cols warpN*32 .. +32

    // ---- stage weights (once) ----
    {
        const int4* srcH = (const int4*)g_W2Th;
        const int4* srcL = (const int4*)g_W2Tl;
        int4* dstB = (int4*)sBW;
        for (int idx = tid; idx < 576; idx += 256) {
            dstB[idx] = srcH[idx];
            dstB[idx + 576] = srcL[idx];
        }
        if (tid < 144) {
            ((int4*)sW3)[tid]       = ((const int4*)g_W3Th)[tid];
            ((int4*)sW3)[tid + 144] = ((const int4*)g_W3Tl)[tid];
        }
        if (tid < 64) sB2[tid] = b2[tid];
        if (tid < 16) sB3[tid] = (tid == 0) ? be[0] : (tid < 9 ? bt[tid - 1] : 0.f);
    }
    __syncthreads();

    // ---- load this warp's B-half into registers (once) ----
    // lane-split: lanes 0-15 -> BH rows, lanes 16-31 -> BL rows.
    uint32_t bc[4][4][4];
    {
        const uint32_t bbase = smem_u32(sBW) + ((lane >= 16) ? 9216u : 0u)
                             + (uint32_t)warpN * 32 * 144
                             + (uint32_t)(lane & 7) * 144 + ((lane >> 3) & 1) * 16;
#pragma unroll
        for (int kt = 0; kt < 4; kt++)
#pragma unroll
            for (int nt = 0; nt < 4; nt++)
                LDSM_X4(bc[kt][nt][0], bc[kt][nt][1], bc[kt][nt][2], bc[kt][nt][3],
                        bbase + (uint32_t)nt * 1152 + kt * 32);
    }

    const uint32_t w3base = smem_u32(sW3) + ((lane >= 16) ? 2304u : 0u)
                          + (uint32_t)(lane & 7) * 144 + ((lane >> 3) & 1) * 16;
    const int g  = lane >> 2;
    const int t2 = (lane & 3) * 2;
    const int tg = lane & 3;
    const int n0 = warpN * 32;
    float* sOutP = warpN ? sOut1 : sOut0;
    const float2 zf = make_float2(0.f, 0.f);

    // ---- persistent tile loop: id = i*32 + jt (64-wide j chunks) ----
    for (int id = blockIdx.x; id < NN * 32; id += NCTAS) {
        const int i  = id >> 5;
        const int jt = id & 31;
        int jlo = jt * 64; if (i + 1 > jlo) jlo = i + 1;
        int jhi = jt * 64 + 64; if (jhi > NN) jhi = NN;
        if (jlo >= jhi) continue;
        const int cnt = jhi - jlo;

        // per-lane A geometry for this tile
        const int j0 = jlo + warpM * 16 + g;
        const int j1 = j0 + 8;
        const bool ok0 = (j0 < jhi);
        const bool ok1 = (j1 < jhi);
        const float2* B0 = (const float2*)(g_B + (size_t)j0 * 64);
        const float2* B1 = (const float2*)(g_B + (size_t)j1 * 64);
        const float* Ai = g_A + (size_t)i * 64;

        float acc[4][4];
#pragma unroll
        for (int nt = 0; nt < 4; nt++)
#pragma unroll
            for (int c = 0; c < 4; c++) acc[nt][c] = 0.f;

#pragma unroll
        for (int kt = 0; kt < 4; kt++) {
            const float2 a0 = __ldg((const float2*)(Ai + kt * 16 + t2));
            const float2 a1 = __ldg((const float2*)(Ai + kt * 16 + t2 + 8));
            const int c2 = kt * 8 + (t2 >> 1);
            const float2 b00 = ok0 ? B0[c2]     : zf;
            const float2 b01 = ok0 ? B0[c2 + 4] : zf;
            const float2 b10 = ok1 ? B1[c2]     : zf;
            const float2 b11 = ok1 ? B1[c2 + 4] : zf;
            const float v00 = fmaxf(a0.x + b00.x, 0.f);
            const float v01 = fmaxf(a0.y + b00.y, 0.f);
            const float v02 = fmaxf(a1.x + b01.x, 0.f);
            const float v03 = fmaxf(a1.y + b01.y, 0.f);
            const float v10 = fmaxf(a0.x + b10.x, 0.f);
            const float v11 = fmaxf(a0.y + b10.y, 0.f);
            const float v12 = fmaxf(a1.x + b11.x, 0.f);
            const float v13 = fmaxf(a1.y + b11.y, 0.f);
            const uint32_t ah0 = __byte_perm(__float_as_uint(v00), __float_as_uint(v01), 0x7632);
            const uint32_t ah1 = __byte_perm(__float_as_uint(v10), __float_as_uint(v11), 0x7632);
            const uint32_t ah2 = __byte_perm(__float_as_uint(v02), __float_as_uint(v03), 0x7632);
            const uint32_t ah3 = __byte_perm(__float_as_uint(v12), __float_as_uint(v13), 0x7632);
            const uint32_t al0 = packbf(resid(v01), resid(v00));
            const uint32_t al1 = packbf(resid(v11), resid(v10));
            const uint32_t al2 = packbf(resid(v03), resid(v02));
            const uint32_t al3 = packbf(resid(v13), resid(v12));
#pragma unroll
            for (int nt = 0; nt < 4; nt++) {
                mma_bf16(acc[nt], ah0, ah1, ah2, ah3, bc[kt][nt][0], bc[kt][nt][1]);
                mma_bf16(acc[nt], ah0, ah1, ah2, ah3, bc[kt][nt][2], bc[kt][nt][3]);
                mma_bf16(acc[nt], al0, al1, al2, al3, bc[kt][nt][0], bc[kt][nt][1]);
            }
        }

        // ---- heads (k-partial per N-warp): relu+bias in regs, C->A refeed ----
        {
            float oacc[2][4];
#pragma unroll
            for (int no = 0; no < 2; no++)
#pragma unroll
                for (int c = 0; c < 4; c++) oacc[no][c] = 0.f;

#pragma unroll
            for (int t = 0; t < 2; t++) {
                const int kh = warpN * 2 + t;   // heads k-tile (of 4)
                const float2 bA = *(const float2*)(sB2 + n0 + (2 * t) * 8 + tg * 2);
                const float2 bB = *(const float2*)(sB2 + n0 + (2 * t + 1) * 8 + tg * 2);
                const float va0 = fmaxf(acc[2 * t][0] + bA.x, 0.f);
                const float va1 = fmaxf(acc[2 * t][1] + bA.y, 0.f);
                const float va2 = fmaxf(acc[2 * t][2] + bA.x, 0.f);
                const float va3 = fmaxf(acc[2 * t][3] + bA.y, 0.f);
                const float vb0 = fmaxf(acc[2 * t + 1][0] + bB.x, 0.f);
                const float vb1 = fmaxf(acc[2 * t + 1][1] + bB.y, 0.f);
                const float vb2 = fmaxf(acc[2 * t + 1][2] + bB.x, 0.f);
                const float vb3 = fmaxf(acc[2 * t + 1][3] + bB.y, 0.f);
                const uint32_t a0 = __byte_perm(__float_as_uint(va0), __float_as_uint(va1), 0x7632);
                const uint32_t a1 = __byte_perm(__float_as_uint(va2), __float_as_uint(va3), 0x7632);
                const uint32_t a2 = __byte_perm(__float_as_uint(vb0), __float_as_uint(vb1), 0x7632);
                const uint32_t a3 = __byte_perm(__float_as_uint(vb2), __float_as_uint(vb3), 0x7632);
                const uint32_t la0 = packbf(resid(va1), resid(va0));
                const uint32_t la1 = packbf(resid(va3), resid(va2));
                const uint32_t la2 = packbf(resid(vb1), resid(vb0));
                const uint32_t la3 = packbf(resid(vb3), resid(vb2));
#pragma unroll
                for (int no = 0; no < 2; no++) {
                    uint32_t bh0, bh1, bl0, bl1;
                    LDSM_X4(bh0, bh1, bl0, bl1,
                            w3base + (uint32_t)no * 1152 + (uint32_t)kh * 32);
                    mma_bf16(oacc[no], a0, a1, a2, a3, bh0, bh1);
                    mma_bf16(oacc[no], a0, a1, a2, a3, bl0, bl1);
                    mma_bf16(oacc[no], la0, la1, la2, la3, bh0, bh1);
                }
            }

            // partial store (pitch 9); N-warp 0 folds head biases
            const int r0 = warpM * 16 + (lane >> 2);
            const int r1 = r0 + 8;
            const int c0 = tg * 2;
            const float be0 = warpN ? 0.f : sB3[c0];
            const float be1 = warpN ? 0.f : sB3[c0 + 1];
            sOutP[r0 * 9 + c0]     = oacc[0][0] + be0;
            sOutP[r0 * 9 + c0 + 1] = oacc[0][1] + be1;
            sOutP[r1 * 9 + c0]     = oacc[0][2] + be0;
            sOutP[r1 * 9 + c0 + 1] = oacc[0][3] + be1;
            if (tg == 0) {
                const float be8 = warpN ? 0.f : sB3[8];
                sOutP[r0 * 9 + 8] = oacc[1][0] + be8;
                sOutP[r1 * 9 + 8] = oacc[1][2] + be8;
            }
        }
        __syncthreads();

        // ---- combine partials + packed-triu contiguous store ----
        const size_t pair0 = (size_t)i * (2 * NN - i - 1) / 2 + (size_t)(jlo - i - 1);
        float* gdst = out + pair0 * 9;
        const int tot = cnt * 9;
        for (int idx = tid; idx < tot; idx += 256)
            gdst[idx] = sOut0[idx] + sOut1[idx];
        __syncthreads();
    }
}

extern "C" void kernel_launch(void* const* d_in, const int* in_sizes, int n_in,
                              void* d_out, int out_size) {
    (void)in_sizes; (void)n_in; (void)out_size;
    const float* X  = (const float*)d_in[0];
    const float* W1 = (const float*)d_in[1];
    const float* b1 = (const float*)d_in[2];
    const float* W2 = (const float*)d_in[3];
    const float* b2 = (const float*)d_in[4];
    const float* We = (const float*)d_in[5];
    const float* be = (const float*)d_in[6];
    const float* Wt = (const float*)d_in[7];
    const float* bt = (const float*)d_in[8];
    float* out = (float*)d_out;

    precompute_kernel<<<NN + 1, DD>>>(X, W1, b1, W2, We, Wt);
    edge_main<<<NCTAS, 256>>>(b2, be, bt, out);
}

// round 11
// speedup vs baseline: 1.4370x; 1.4370x over previous
#include <cuda_runtime.h>
#include <cuda_fp16.h>
#include <cstdint>

#define NN 2048
#define DD 64

// ---------------- device scratch ----------------
__device__ float g_A[NN * DD];                       // A[i] = x_i @ W1[:64] + b1
__device__ float g_B[NN * DD];                       // B[j] = x_j @ W1[64:]
__device__ __align__(16) unsigned short g_W2Th[64 * 72];  // W2^T hi (fp16), [n][k] pitch 72
__device__ __align__(16) unsigned short g_W2Tl[64 * 72];  // W2^T lo (fp16)
__device__ __align__(16) unsigned short g_W3Th[16 * 72];  // W3^T hi
__device__ __align__(16) unsigned short g_W3Tl[16 * 72];  // W3^T lo

// ---------------- helpers ----------------
__device__ __forceinline__ uint32_t smem_u32(const void* p) {
    uint32_t a;
    asm("{ .reg .u64 t; cvta.to.shared.u64 t, %1; cvt.u32.u64 %0, t; }" : "=r"(a) : "l"(p));
    return a;
}
// pack two floats to f16x2: low half = lo, high half = hi
__device__ __forceinline__ uint32_t packf16(float hi, float lo) {
    uint32_t r; asm("cvt.rn.f16x2.f32 %0, %1, %2;" : "=r"(r) : "f"(hi), "f"(lo)); return r;
}

#define LDSM_X4(r0, r1, r2, r3, addr) \
    asm volatile("ldmatrix.sync.aligned.m8n8.x4.shared.b16 {%0,%1,%2,%3}, [%4];" \
        : "=r"(r0), "=r"(r1), "=r"(r2), "=r"(r3) : "r"(addr))

__device__ __forceinline__ void mma_f16(float* c, uint32_t a0, uint32_t a1,
                                        uint32_t a2, uint32_t a3,
                                        uint32_t b0, uint32_t b1) {
    asm volatile(
        "mma.sync.aligned.m16n8k16.row.col.f32.f16.f16.f32 "
        "{%0,%1,%2,%3}, {%4,%5,%6,%7}, {%8,%9}, {%0,%1,%2,%3};"
        : "+f"(c[0]), "+f"(c[1]), "+f"(c[2]), "+f"(c[3])
        : "r"(a0), "r"(a1), "r"(a2), "r"(a3), "r"(b0), "r"(b1));
}

// ---------------- Kernel 1: precompute A/B rows + weight tiles ----------------
__global__ void precompute_kernel(const float* __restrict__ X,
                                  const float* __restrict__ W1,
                                  const float* __restrict__ b1,
                                  const float* __restrict__ W2,
                                  const float* __restrict__ We,
                                  const float* __restrict__ Wt) {
    if (blockIdx.x < NN) {
        __shared__ float xs[DD];
        const int i = blockIdx.x;
        const int d = threadIdx.x;
        xs[d] = X[i * DD + d];
        __syncthreads();
        float a = b1[d], b = 0.f;
#pragma unroll 8
        for (int k = 0; k < DD; k++) {
            const float xv = xs[k];
            a = fmaf(xv, __ldg(&W1[k * DD + d]), a);
            b = fmaf(xv, __ldg(&W1[(DD + k) * DD + d]), b);
        }
        g_A[i * DD + d] = a;
        g_B[i * DD + d] = b;
    } else {
        const int t = threadIdx.x;
        for (int idx = t; idx < 64 * 72; idx += 64) {
            const int n = idx / 72, k = idx % 72;
            float v = (k < 64) ? W2[k * 64 + n] : 0.f;
            __half h = __float2half_rn(v);
            g_W2Th[idx] = __half_as_ushort(h);
            g_W2Tl[idx] = __half_as_ushort(__float2half_rn(v - __half2float(h)));
        }
        for (int idx = t; idx < 16 * 72; idx += 64) {
            const int n = idx / 72, k = idx % 72;
            float v = 0.f;
            if (k < 64) {
                if (n == 0) v = We[k];
                else if (n < 9) v = Wt[k * 8 + n - 1];
            }
            __half h = __float2half_rn(v);
            g_W3Th[idx] = __half_as_ushort(h);
            g_W3Tl[idx] = __half_as_ushort(__float2half_rn(v - __half2float(h)));
        }
    }
}

// ---------------- Kernel 2: main pair kernel (fp16 2-pass) ----------------
// Static SMEM: 46,400 B -> 2 CTA/SM without opt-in.
__global__ __launch_bounds__(256, 2) void edge_main(
    const float* __restrict__ b2,
    const float* __restrict__ be, const float* __restrict__ bt,
    float* __restrict__ out)
{
    __shared__ __align__(16) unsigned short sA[128 * 72];       // Ah (fp16), pitch 72
    __shared__ __align__(16) unsigned short sBW[2 * 64 * 72];   // BH | BL
    __shared__ __align__(16) unsigned short sW3[2 * 16 * 72];   // W3 hi | lo
    __shared__ __align__(16) float sOut[128 * 9];
    __shared__ __align__(16) float sB2[64];
    __shared__ float sB3[16];

    const int i  = blockIdx.y;
    const int jt = blockIdx.x;
    int jlo = jt * 128; if (i + 1 > jlo) jlo = i + 1;
    int jhi = jt * 128 + 128; if (jhi > NN) jhi = NN;
    if (jlo >= jhi) return;
    const int cnt = jhi - jlo;

    const int tid  = threadIdx.x;
    const int warp = tid >> 5;
    const int lane = tid & 31;

    // ---- stage weights ----
    {
        const int4* srcH = (const int4*)g_W2Th;
        const int4* srcL = (const int4*)g_W2Tl;
        int4* dstB = (int4*)sBW;
        for (int idx = tid; idx < 576; idx += 256) {
            dstB[idx] = srcH[idx];
            dstB[idx + 576] = srcL[idx];
        }
        if (tid < 144) {
            ((int4*)sW3)[tid]       = ((const int4*)g_W3Th)[tid];
            ((int4*)sW3)[tid + 144] = ((const int4*)g_W3Tl)[tid];
        }
        if (tid < 64) sB2[tid] = b2[tid];
        if (tid < 16) sB3[tid] = (tid == 0) ? be[0] : (tid < 9 ? bt[tid - 1] : 0.f);
    }

    // ---- stage Ah only: h1 = relu(A[i]+B[j]) -> fp16 ----
    {
        const float4* gB4 = (const float4*)g_B;
        const float4* gA4 = (const float4*)g_A;
#pragma unroll
        for (int it = 0; it < 8; it++) {
            const int idx = tid + it * 256;
            const int m = idx >> 4, kq = idx & 15;
            const int j = jlo + m;
            float4 v = make_float4(0.f, 0.f, 0.f, 0.f);
            if (j < jhi) {
                const float4 b4 = gB4[j * 16 + kq];
                const float4 a4 = __ldg(&gA4[i * 16 + kq]);
                v.x = fmaxf(a4.x + b4.x, 0.f);
                v.y = fmaxf(a4.y + b4.y, 0.f);
                v.z = fmaxf(a4.z + b4.z, 0.f);
                v.w = fmaxf(a4.w + b4.w, 0.f);
            }
            uint2 hp;
            hp.x = packf16(v.y, v.x);
            hp.y = packf16(v.w, v.z);
            *(uint2*)(sA + m * 72 + kq * 4) = hp;
        }
    }
    __syncthreads();

    // ---- 2-pass GEMM: acc = Ah*Bh + Ah*Bl ----
    float acc[8][4];
#pragma unroll
    for (int nt = 0; nt < 8; nt++)
#pragma unroll
        for (int c = 0; c < 4; c++) acc[nt][c] = 0.f;

    const uint32_t ahbase = smem_u32(sA)
                          + (uint32_t)(warp * 16 + (lane & 15)) * 144 + (lane >> 4) * 16;
    // per-lane combined hi/lo B address: lanes 0-15 -> BH, 16-31 -> BL
    const uint32_t bbase = smem_u32(sBW) + ((lane >= 16) ? 9216u : 0u)
                         + (uint32_t)(lane & 7) * 144 + ((lane >> 3) & 1) * 16;
    const uint32_t w3base = smem_u32(sW3) + ((lane >= 16) ? 2304u : 0u)
                          + (uint32_t)(lane & 7) * 144 + ((lane >> 3) & 1) * 16;

#pragma unroll
    for (int kt = 0; kt < 4; kt++) {
        uint32_t a0, a1, a2, a3;
        LDSM_X4(a0, a1, a2, a3, ahbase + kt * 32);
#pragma unroll
        for (int nt = 0; nt < 8; nt++) {
            uint32_t bh0, bh1, bl0, bl1;
            LDSM_X4(bh0, bh1, bl0, bl1, bbase + (uint32_t)nt * 1152 + kt * 32);
            mma_f16(acc[nt], a0, a1, a2, a3, bh0, bh1);
            mma_f16(acc[nt], a0, a1, a2, a3, bl0, bl1);
        }
    }

    // ---- heads: relu+bias in regs, C->A fragment refeed, 2-pass vs W3 hi/lo ----
    {
        const int tg = lane & 3;
        float oacc[2][4];
#pragma unroll
        for (int no = 0; no < 2; no++)
#pragma unroll
            for (int c = 0; c < 4; c++) oacc[no][c] = 0.f;

#pragma unroll
        for (int kt = 0; kt < 4; kt++) {
            const float2 bA = *(const float2*)(sB2 + (2 * kt) * 8 + tg * 2);
            const float2 bB = *(const float2*)(sB2 + (2 * kt + 1) * 8 + tg * 2);
            const float va0 = fmaxf(acc[2 * kt][0] + bA.x, 0.f);
            const float va1 = fmaxf(acc[2 * kt][1] + bA.y, 0.f);
            const float va2 = fmaxf(acc[2 * kt][2] + bA.x, 0.f);
            const float va3 = fmaxf(acc[2 * kt][3] + bA.y, 0.f);
            const float vb0 = fmaxf(acc[2 * kt + 1][0] + bB.x, 0.f);
            const float vb1 = fmaxf(acc[2 * kt + 1][1] + bB.y, 0.f);
            const float vb2 = fmaxf(acc[2 * kt + 1][2] + bB.x, 0.f);
            const float vb3 = fmaxf(acc[2 * kt + 1][3] + bB.y, 0.f);
            const uint32_t a0 = packf16(va1, va0);
            const uint32_t a1 = packf16(va3, va2);
            const uint32_t a2 = packf16(vb1, vb0);
            const uint32_t a3 = packf16(vb3, vb2);
#pragma unroll
            for (int no = 0; no < 2; no++) {
                uint32_t bh0, bh1, bl0, bl1;
                LDSM_X4(bh0, bh1, bl0, bl1, w3base + (uint32_t)no * 1152 + kt * 32);
                mma_f16(oacc[no], a0, a1, a2, a3, bh0, bh1);
                mma_f16(oacc[no], a0, a1, a2, a3, bl0, bl1);
            }
        }

        // store to sOut (pitch 9): cols 0-7 from tile 0, col 8 from tile 1
        const int r0 = warp * 16 + (lane >> 2);
        const int r1 = r0 + 8;
        const int c0 = tg * 2;
        sOut[r0 * 9 + c0]     = oacc[0][0] + sB3[c0];
        sOut[r0 * 9 + c0 + 1] = oacc[0][1] + sB3[c0 + 1];
        sOut[r1 * 9 + c0]     = oacc[0][2] + sB3[c0];
        sOut[r1 * 9 + c0 + 1] = oacc[0][3] + sB3[c0 + 1];
        if (tg == 0) {
            sOut[r0 * 9 + 8] = oacc[1][0] + sB3[8];
            sOut[r1 * 9 + 8] = oacc[1][2] + sB3[8];
        }
    }
    __syncthreads();

    // ---- packed-triu contiguous store ----
    const size_t pair0 = (size_t)i * (2 * NN - i - 1) / 2 + (size_t)(jlo - i - 1);
    float* gdst = out + pair0 * 9;
    const int tot = cnt * 9;
    for (int idx = tid; idx < tot; idx += 256) gdst[idx] = sOut[idx];
}

extern "C" void kernel_launch(void* const* d_in, const int* in_sizes, int n_in,
                              void* d_out, int out_size) {
    (void)in_sizes; (void)n_in; (void)out_size;
    const float* X  = (const float*)d_in[0];
    const float* W1 = (const float*)d_in[1];
    const float* b1 = (const float*)d_in[2];
    const float* W2 = (const float*)d_in[3];
    const float* b2 = (const float*)d_in[4];
    const float* We = (const float*)d_in[5];
    const float* be = (const float*)d_in[6];
    const float* Wt = (const float*)d_in[7];
    const float* bt = (const float*)d_in[8];
    float* out = (float*)d_out;

    precompute_kernel<<<NN + 1, DD>>>(X, W1, b1, W2, We, Wt);

    dim3 grid(NN / 128, NN);
    edge_main<<<grid, 256>>>(b2, be, bt, out);
}

// round 12
// speedup vs baseline: 1.7774x; 1.2369x over previous
#include <cuda_runtime.h>
#include <cuda_fp16.h>
#include <cstdint>

#define NN 2048
#define DD 64

// ---------------- device scratch ----------------
__device__ float g_A[NN * DD];                       // A[i] = x_i @ W1[:64] + b1
__device__ float g_B[NN * DD];                       // B[j] = x_j @ W1[64:]
__device__ __align__(16) unsigned short g_W2T[64 * 72];   // W2^T fp16, [n][k] pitch 72
__device__ __align__(16) unsigned short g_W3T[16 * 72];   // W3^T fp16

// ---------------- helpers ----------------
__device__ __forceinline__ uint32_t smem_u32(const void* p) {
    uint32_t a;
    asm("{ .reg .u64 t; cvta.to.shared.u64 t, %1; cvt.u32.u64 %0, t; }" : "=r"(a) : "l"(p));
    return a;
}
// pack two floats to f16x2: low half = lo, high half = hi
__device__ __forceinline__ uint32_t packf16(float hi, float lo) {
    uint32_t r; asm("cvt.rn.f16x2.f32 %0, %1, %2;" : "=r"(r) : "f"(hi), "f"(lo)); return r;
}

#define LDSM_X4(r0, r1, r2, r3, addr) \
    asm volatile("ldmatrix.sync.aligned.m8n8.x4.shared.b16 {%0,%1,%2,%3}, [%4];" \
        : "=r"(r0), "=r"(r1), "=r"(r2), "=r"(r3) : "r"(addr))

__device__ __forceinline__ void mma_f16(float* c, uint32_t a0, uint32_t a1,
                                        uint32_t a2, uint32_t a3,
                                        uint32_t b0, uint32_t b1) {
    asm volatile(
        "mma.sync.aligned.m16n8k16.row.col.f32.f16.f16.f32 "
        "{%0,%1,%2,%3}, {%4,%5,%6,%7}, {%8,%9}, {%0,%1,%2,%3};"
        : "+f"(c[0]), "+f"(c[1]), "+f"(c[2]), "+f"(c[3])
        : "r"(a0), "r"(a1), "r"(a2), "r"(a3), "r"(b0), "r"(b1));
}

// ---------------- Kernel 1: precompute A/B rows + weight tiles ----------------
__global__ void precompute_kernel(const float* __restrict__ X,
                                  const float* __restrict__ W1,
                                  const float* __restrict__ b1,
                                  const float* __restrict__ W2,
                                  const float* __restrict__ We,
                                  const float* __restrict__ Wt) {
    if (blockIdx.x < NN) {
        __shared__ float xs[DD];
        const int i = blockIdx.x;
        const int d = threadIdx.x;
        xs[d] = X[i * DD + d];
        __syncthreads();
        float a = b1[d], b = 0.f;
#pragma unroll 8
        for (int k = 0; k < DD; k++) {
            const float xv = xs[k];
            a = fmaf(xv, __ldg(&W1[k * DD + d]), a);
            b = fmaf(xv, __ldg(&W1[(DD + k) * DD + d]), b);
        }
        g_A[i * DD + d] = a;
        g_B[i * DD + d] = b;
    } else {
        const int t = threadIdx.x;
        for (int idx = t; idx < 64 * 72; idx += 64) {
            const int n = idx / 72, k = idx % 72;
            float v = (k < 64) ? W2[k * 64 + n] : 0.f;
            g_W2T[idx] = __half_as_ushort(__float2half_rn(v));
        }
        for (int idx = t; idx < 16 * 72; idx += 64) {
            const int n = idx / 72, k = idx % 72;
            float v = 0.f;
            if (k < 64) {
                if (n == 0) v = We[k];
                else if (n < 9) v = Wt[k * 8 + n - 1];
            }
            g_W3T[idx] = __half_as_ushort(__float2half_rn(v));
        }
    }
}

// ---------------- Kernel 2: main pair kernel (fp16 hi-only, 1-pass) --------
// Static SMEM ~35 KB. One LDSM_X4 feeds TWO nt tiles (lanes 0-15 -> nt even,
// lanes 16-31 -> nt odd); same packing for the two W3 row-tiles.
__global__ __launch_bounds__(256, 2) void edge_main(
    const float* __restrict__ b2,
    const float* __restrict__ be, const float* __restrict__ bt,
    float* __restrict__ out)
{
    __shared__ __align__(16) unsigned short sA[128 * 72];   // h1 fp16, pitch 72
    __shared__ __align__(16) unsigned short sB[64 * 72];    // W2^T fp16
    __shared__ __align__(16) unsigned short sW3[16 * 72];   // W3^T fp16
    __shared__ __align__(16) float sOut[128 * 9];
    __shared__ __align__(16) float sB2[64];
    __shared__ float sB3[16];

    const int i  = blockIdx.y;
    const int jt = blockIdx.x;
    int jlo = jt * 128; if (i + 1 > jlo) jlo = i + 1;
    int jhi = jt * 128 + 128; if (jhi > NN) jhi = NN;
    if (jlo >= jhi) return;
    const int cnt = jhi - jlo;

    const int tid  = threadIdx.x;
    const int warp = tid >> 5;
    const int lane = tid & 31;

    // ---- stage weights ----
    {
        const int4* srcB = (const int4*)g_W2T;
        int4* dstB = (int4*)sB;
        for (int idx = tid; idx < 576; idx += 256) dstB[idx] = srcB[idx];
        if (tid < 144) ((int4*)sW3)[tid] = ((const int4*)g_W3T)[tid];
        if (tid < 64) sB2[tid] = b2[tid];
        if (tid < 16) sB3[tid] = (tid == 0) ? be[0] : (tid < 9 ? bt[tid - 1] : 0.f);
    }

    // ---- stage h1 = relu(A[i]+B[j]) -> fp16 ----
    {
        const float4* gB4 = (const float4*)g_B;
        const float4* gA4 = (const float4*)g_A;
#pragma unroll
        for (int it = 0; it < 8; it++) {
            const int idx = tid + it * 256;
            const int m = idx >> 4, kq = idx & 15;
            const int j = jlo + m;
            float4 v = make_float4(0.f, 0.f, 0.f, 0.f);
            if (j < jhi) {
                const float4 b4 = gB4[j * 16 + kq];
                const float4 a4 = __ldg(&gA4[i * 16 + kq]);
                v.x = fmaxf(a4.x + b4.x, 0.f);
                v.y = fmaxf(a4.y + b4.y, 0.f);
                v.z = fmaxf(a4.z + b4.z, 0.f);
                v.w = fmaxf(a4.w + b4.w, 0.f);
            }
            uint2 hp;
            hp.x = packf16(v.y, v.x);
            hp.y = packf16(v.w, v.z);
            *(uint2*)(sA + m * 72 + kq * 4) = hp;
        }
    }
    __syncthreads();

    // ---- 1-pass fp16 GEMM ----
    float acc[8][4];
#pragma unroll
    for (int nt = 0; nt < 8; nt++)
#pragma unroll
        for (int c = 0; c < 4; c++) acc[nt][c] = 0.f;

    const uint32_t ahbase = smem_u32(sA)
                          + (uint32_t)(warp * 16 + (lane & 15)) * 144 + (lane >> 4) * 16;
    // dual-nt B address: lanes 0-15 -> nt even rows, lanes 16-31 -> nt odd rows
    const uint32_t bbase = smem_u32(sB) + ((lane >= 16) ? 1152u : 0u)
                         + (uint32_t)(lane & 7) * 144 + ((lane >> 3) & 1) * 16;
    // dual-no W3 address: lanes 0-15 -> rows 0-7 (no=0), lanes 16-31 -> rows 8-15 (no=1)
    const uint32_t w3base = smem_u32(sW3) + ((lane >= 16) ? 8u * 144u : 0u)
                          + (uint32_t)(lane & 7) * 144 + ((lane >> 3) & 1) * 16;

#pragma unroll
    for (int kt = 0; kt < 4; kt++) {
        uint32_t a0, a1, a2, a3;
        LDSM_X4(a0, a1, a2, a3, ahbase + kt * 32);
#pragma unroll
        for (int ntp = 0; ntp < 4; ntp++) {
            uint32_t b0, b1, b2v, b3v;
            LDSM_X4(b0, b1, b2v, b3v, bbase + (uint32_t)ntp * 2304 + kt * 32);
            mma_f16(acc[2 * ntp],     a0, a1, a2, a3, b0, b1);
            mma_f16(acc[2 * ntp + 1], a0, a1, a2, a3, b2v, b3v);
        }
    }

    // ---- heads: relu+bias in regs, C->A fragment refeed, 1-pass vs W3 ----
    {
        const int tg = lane & 3;
        float oacc[2][4];
#pragma unroll
        for (int no = 0; no < 2; no++)
#pragma unroll
            for (int c = 0; c < 4; c++) oacc[no][c] = 0.f;

#pragma unroll
        for (int kt = 0; kt < 4; kt++) {
            const float2 bA = *(const float2*)(sB2 + (2 * kt) * 8 + tg * 2);
            const float2 bB = *(const float2*)(sB2 + (2 * kt + 1) * 8 + tg * 2);
            const float va0 = fmaxf(acc[2 * kt][0] + bA.x, 0.f);
            const float va1 = fmaxf(acc[2 * kt][1] + bA.y, 0.f);
            const float va2 = fmaxf(acc[2 * kt][2] + bA.x, 0.f);
            const float va3 = fmaxf(acc[2 * kt][3] + bA.y, 0.f);
            const float vb0 = fmaxf(acc[2 * kt + 1][0] + bB.x, 0.f);
            const float vb1 = fmaxf(acc[2 * kt + 1][1] + bB.y, 0.f);
            const float vb2 = fmaxf(acc[2 * kt + 1][2] + bB.x, 0.f);
            const float vb3 = fmaxf(acc[2 * kt + 1][3] + bB.y, 0.f);
            const uint32_t a0 = packf16(va1, va0);
            const uint32_t a1 = packf16(va3, va2);
            const uint32_t a2 = packf16(vb1, vb0);
            const uint32_t a3 = packf16(vb3, vb2);
            uint32_t w0, w1, w2, w3;
            LDSM_X4(w0, w1, w2, w3, w3base + kt * 32);
            mma_f16(oacc[0], a0, a1, a2, a3, w0, w1);
            mma_f16(oacc[1], a0, a1, a2, a3, w2, w3);
        }

        // store to sOut (pitch 9): cols 0-7 from tile 0, col 8 from tile 1
        const int r0 = warp * 16 + (lane >> 2);
        const int r1 = r0 + 8;
        const int c0 = tg * 2;
        sOut[r0 * 9 + c0]     = oacc[0][0] + sB3[c0];
        sOut[r0 * 9 + c0 + 1] = oacc[0][1] + sB3[c0 + 1];
        sOut[r1 * 9 + c0]     = oacc[0][2] + sB3[c0];
        sOut[r1 * 9 + c0 + 1] = oacc[0][3] + sB3[c0 + 1];
        if (tg == 0) {
            sOut[r0 * 9 + 8] = oacc[1][0] + sB3[8];
            sOut[r1 * 9 + 8] = oacc[1][2] + sB3[8];
        }
    }
    __syncthreads();

    // ---- packed-triu contiguous store ----
    const size_t pair0 = (size_t)i * (2 * NN - i - 1) / 2 + (size_t)(jlo - i - 1);
    float* gdst = out + pair0 * 9;
    const int tot = cnt * 9;
    for (int idx = tid; idx < tot; idx += 256) gdst[idx] = sOut[idx];
}

extern "C" void kernel_launch(void* const* d_in, const int* in_sizes, int n_in,
                              void* d_out, int out_size) {
    (void)in_sizes; (void)n_in; (void)out_size;
    const float* X  = (const float*)d_in[0];
    const float* W1 = (const float*)d_in[1];
    const float* b1 = (const float*)d_in[2];
    const float* W2 = (const float*)d_in[3];
    const float* b2 = (const float*)d_in[4];
    const float* We = (const float*)d_in[5];
    const float* be = (const float*)d_in[6];
    const float* Wt = (const float*)d_in[7];
    const float* bt = (const float*)d_in[8];
    float* out = (float*)d_out;

    precompute_kernel<<<NN + 1, DD>>>(X, W1, b1, W2, We, Wt);

    dim3 grid(NN / 128, NN);
    edge_main<<<grid, 256>>>(b2, be, bt, out);
}

// round 13
// speedup vs baseline: 2.1158x; 1.1904x over previous
#include <cuda_runtime.h>
#include <cuda_fp16.h>
#include <cstdint>

#define NN 2048
#define DD 64
#define MT 256

// ---------------- device scratch ----------------
__device__ float g_A[NN * DD];                       // A[i] = x_i @ W1[:64] + b1
__device__ float g_B[NN * DD];                       // B[j] = x_j @ W1[64:]
__device__ __align__(16) unsigned short g_W2T[64 * 72];   // W2^T fp16, [n][k] pitch 72
__device__ __align__(16) unsigned short g_W3T[16 * 72];   // W3^T fp16

// ---------------- helpers ----------------
__device__ __forceinline__ uint32_t smem_u32(const void* p) {
    uint32_t a;
    asm("{ .reg .u64 t; cvta.to.shared.u64 t, %1; cvt.u32.u64 %0, t; }" : "=r"(a) : "l"(p));
    return a;
}
__device__ __forceinline__ uint32_t packf16(float hi, float lo) {
    uint32_t r; asm("cvt.rn.f16x2.f32 %0, %1, %2;" : "=r"(r) : "f"(hi), "f"(lo)); return r;
}

#define LDSM_X4(r0, r1, r2, r3, addr) \
    asm volatile("ldmatrix.sync.aligned.m8n8.x4.shared.b16 {%0,%1,%2,%3}, [%4];" \
        : "=r"(r0), "=r"(r1), "=r"(r2), "=r"(r3) : "r"(addr))

__device__ __forceinline__ void mma_f16(float* c, uint32_t a0, uint32_t a1,
                                        uint32_t a2, uint32_t a3,
                                        uint32_t b0, uint32_t b1) {
    asm volatile(
        "mma.sync.aligned.m16n8k16.row.col.f32.f16.f16.f32 "
        "{%0,%1,%2,%3}, {%4,%5,%6,%7}, {%8,%9}, {%0,%1,%2,%3};"
        : "+f"(c[0]), "+f"(c[1]), "+f"(c[2]), "+f"(c[3])
        : "r"(a0), "r"(a1), "r"(a2), "r"(a3), "r"(b0), "r"(b1));
}

// ---------------- Kernel 1: precompute A/B rows + weight tiles ----------------
__global__ void precompute_kernel(const float* __restrict__ X,
                                  const float* __restrict__ W1,
                                  const float* __restrict__ b1,
                                  const float* __restrict__ W2,
                                  const float* __restrict__ We,
                                  const float* __restrict__ Wt) {
    if (blockIdx.x < NN) {
        __shared__ float xs[DD];
        const int i = blockIdx.x;
        const int d = threadIdx.x;
        xs[d] = X[i * DD + d];
        __syncthreads();
        float a = b1[d], b = 0.f;
#pragma unroll 8
        for (int k = 0; k < DD; k++) {
            const float xv = xs[k];
            a = fmaf(xv, __ldg(&W1[k * DD + d]), a);
            b = fmaf(xv, __ldg(&W1[(DD + k) * DD + d]), b);
        }
        g_A[i * DD + d] = a;
        g_B[i * DD + d] = b;
    } else {
        const int t = threadIdx.x;
        for (int idx = t; idx < 64 * 72; idx += 64) {
            const int n = idx / 72, k = idx % 72;
            float v = (k < 64) ? W2[k * 64 + n] : 0.f;
            g_W2T[idx] = __half_as_ushort(__float2half_rn(v));
        }
        for (int idx = t; idx < 16 * 72; idx += 64) {
            const int n = idx / 72, k = idx % 72;
            float v = 0.f;
            if (k < 64) {
                if (n == 0) v = We[k];
                else if (n < 9) v = Wt[k * 8 + n - 1];
            }
            g_W3T[idx] = __half_as_ushort(__float2half_rn(v));
        }
    }
}

// ---------------- SMEM layout (dynamic, 57920 B) ----------------
// sA   [256][72] fp16  @ 0       (36864)
// sB   [64][72]  fp16  @ 36864   (9216)
// sW3  [16][72]  fp16  @ 46080   (2304)
// sOut [256][9]  f32   @ 48384   (9216)
// sB2  [64]      f32   @ 57600   (256)
// sB3  [16]      f32   @ 57856   (64)
#define SMEM_BYTES 57920

// ---------------- Kernel 2: main pair kernel (fp16 1-pass, MT=256) ---------
__global__ __launch_bounds__(256, 2) void edge_main(
    const float* __restrict__ b2,
    const float* __restrict__ be, const float* __restrict__ bt,
    float* __restrict__ out)
{
    extern __shared__ __align__(16) char smem[];
    unsigned short* sA  = (unsigned short*)smem;
    unsigned short* sB  = (unsigned short*)(smem + 36864);
    unsigned short* sW3 = (unsigned short*)(smem + 46080);
    float* sOut = (float*)(smem + 48384);
    float* sB2  = (float*)(smem + 57600);
    float* sB3  = (float*)(smem + 57856);

    const int i  = blockIdx.y;
    const int jt = blockIdx.x;
    int jlo = jt * MT; if (i + 1 > jlo) jlo = i + 1;
    int jhi = jt * MT + MT; if (jhi > NN) jhi = NN;
    if (jlo >= jhi) return;
    const int cnt = jhi - jlo;

    const int tid  = threadIdx.x;
    const int warp = tid >> 5;
    const int lane = tid & 31;

    // ---- stage weights ----
    {
        const int4* srcB = (const int4*)g_W2T;
        int4* dstB = (int4*)sB;
        for (int idx = tid; idx < 576; idx += 256) dstB[idx] = srcB[idx];
        if (tid < 144) ((int4*)sW3)[tid] = ((const int4*)g_W3T)[tid];
        if (tid < 64) sB2[tid] = b2[tid];
        if (tid < 16) sB3[tid] = (tid == 0) ? be[0] : (tid < 9 ? bt[tid - 1] : 0.f);
    }

    // ---- stage h1 = relu(A[i]+B[j]) -> fp16 (256 rows) ----
    {
        const float4* gB4 = (const float4*)g_B;
        const float4* gA4 = (const float4*)g_A;
#pragma unroll
        for (int it = 0; it < 16; it++) {
            const int idx = tid + it * 256;
            const int m = idx >> 4, kq = idx & 15;
            const int j = jlo + m;
            float4 v = make_float4(0.f, 0.f, 0.f, 0.f);
            if (j < jhi) {
                const float4 b4 = gB4[j * 16 + kq];
                const float4 a4 = __ldg(&gA4[i * 16 + kq]);
                v.x = fmaxf(a4.x + b4.x, 0.f);
                v.y = fmaxf(a4.y + b4.y, 0.f);
                v.z = fmaxf(a4.z + b4.z, 0.f);
                v.w = fmaxf(a4.w + b4.w, 0.f);
            }
            uint2 hp;
            hp.x = packf16(v.y, v.x);
            hp.y = packf16(v.w, v.z);
            *(uint2*)(sA + m * 72 + kq * 4) = hp;
        }
    }
    __syncthreads();

    // ---- 1-pass fp16 GEMM, 2 m-tiles per warp (B frags shared) ----
    float acc[2][8][4];
#pragma unroll
    for (int mt = 0; mt < 2; mt++)
#pragma unroll
        for (int nt = 0; nt < 8; nt++)
#pragma unroll
            for (int c = 0; c < 4; c++) acc[mt][nt][c] = 0.f;

    const uint32_t ahbase = smem_u32(sA)
                          + (uint32_t)(warp * 32 + (lane & 15)) * 144 + (lane >> 4) * 16;
    // dual-nt B address: lanes 0-15 -> nt even rows, lanes 16-31 -> nt odd rows
    const uint32_t bbase = smem_u32(sB) + ((lane >= 16) ? 1152u : 0u)
                         + (uint32_t)(lane & 7) * 144 + ((lane >> 3) & 1) * 16;
    // dual-no W3 address: lanes 0-15 -> rows 0-7, lanes 16-31 -> rows 8-15
    const uint32_t w3base = smem_u32(sW3) + ((lane >= 16) ? 8u * 144u : 0u)
                          + (uint32_t)(lane & 7) * 144 + ((lane >> 3) & 1) * 16;

#pragma unroll
    for (int kt = 0; kt < 4; kt++) {
        uint32_t a[2][4];
        LDSM_X4(a[0][0], a[0][1], a[0][2], a[0][3], ahbase + kt * 32);
        LDSM_X4(a[1][0], a[1][1], a[1][2], a[1][3], ahbase + 2304 + kt * 32);
#pragma unroll
        for (int ntp = 0; ntp < 4; ntp++) {
            uint32_t b0, b1, b2v, b3v;
            LDSM_X4(b0, b1, b2v, b3v, bbase + (uint32_t)ntp * 2304 + kt * 32);
#pragma unroll
            for (int mt = 0; mt < 2; mt++) {
                mma_f16(acc[mt][2 * ntp],     a[mt][0], a[mt][1], a[mt][2], a[mt][3], b0, b1);
                mma_f16(acc[mt][2 * ntp + 1], a[mt][0], a[mt][1], a[mt][2], a[mt][3], b2v, b3v);
            }
        }
    }

    // ---- heads: relu+bias in regs, C->A fragment refeed, 1-pass vs W3 ----
    {
        const int tg = lane & 3;
#pragma unroll
        for (int mt = 0; mt < 2; mt++) {
            float oacc[2][4];
#pragma unroll
            for (int no = 0; no < 2; no++)
#pragma unroll
                for (int c = 0; c < 4; c++) oacc[no][c] = 0.f;

#pragma unroll
            for (int kt = 0; kt < 4; kt++) {
                const float2 bA = *(const float2*)(sB2 + (2 * kt) * 8 + tg * 2);
                const float2 bB = *(const float2*)(sB2 + (2 * kt + 1) * 8 + tg * 2);
                const float va0 = fmaxf(acc[mt][2 * kt][0] + bA.x, 0.f);
                const float va1 = fmaxf(acc[mt][2 * kt][1] + bA.y, 0.f);
                const float va2 = fmaxf(acc[mt][2 * kt][2] + bA.x, 0.f);
                const float va3 = fmaxf(acc[mt][2 * kt][3] + bA.y, 0.f);
                const float vb0 = fmaxf(acc[mt][2 * kt + 1][0] + bB.x, 0.f);
                const float vb1 = fmaxf(acc[mt][2 * kt + 1][1] + bB.y, 0.f);
                const float vb2 = fmaxf(acc[mt][2 * kt + 1][2] + bB.x, 0.f);
                const float vb3 = fmaxf(acc[mt][2 * kt + 1][3] + bB.y, 0.f);
                const uint32_t a0 = packf16(va1, va0);
                const uint32_t a1 = packf16(va3, va2);
                const uint32_t a2 = packf16(vb1, vb0);
                const uint32_t a3 = packf16(vb3, vb2);
                uint32_t w0, w1, w2, w3;
                LDSM_X4(w0, w1, w2, w3, w3base + kt * 32);
                mma_f16(oacc[0], a0, a1, a2, a3, w0, w1);
                mma_f16(oacc[1], a0, a1, a2, a3, w2, w3);
            }

            // store to sOut (pitch 9): cols 0-7 from tile 0, col 8 from tile 1
            const int r0 = warp * 32 + mt * 16 + (lane >> 2);
            const int r1 = r0 + 8;
            const int c0 = tg * 2;
            sOut[r0 * 9 + c0]     = oacc[0][0] + sB3[c0];
            sOut[r0 * 9 + c0 + 1] = oacc[0][1] + sB3[c0 + 1];
            sOut[r1 * 9 + c0]     = oacc[0][2] + sB3[c0];
            sOut[r1 * 9 + c0 + 1] = oacc[0][3] + sB3[c0 + 1];
            if (tg == 0) {
                sOut[r0 * 9 + 8] = oacc[1][0] + sB3[8];
                sOut[r1 * 9 + 8] = oacc[1][2] + sB3[8];
            }
        }
    }
    __syncthreads();

    // ---- packed-triu contiguous store ----
    const size_t pair0 = (size_t)i * (2 * NN - i - 1) / 2 + (size_t)(jlo - i - 1);
    float* gdst = out + pair0 * 9;
    const int tot = cnt * 9;
    for (int idx = tid; idx < tot; idx += 256) gdst[idx] = sOut[idx];
}

extern "C" void kernel_launch(void* const* d_in, const int* in_sizes, int n_in,
                              void* d_out, int out_size) {
    (void)in_sizes; (void)n_in; (void)out_size;
    const float* X  = (const float*)d_in[0];
    const float* W1 = (const float*)d_in[1];
    const float* b1 = (const float*)d_in[2];
    const float* W2 = (const float*)d_in[3];
    const float* b2 = (const float*)d_in[4];
    const float* We = (const float*)d_in[5];
    const float* be = (const float*)d_in[6];
    const float* Wt = (const float*)d_in[7];
    const float* bt = (const float*)d_in[8];
    float* out = (float*)d_out;

    cudaFuncSetAttribute(edge_main, cudaFuncAttributeMaxDynamicSharedMemorySize, SMEM_BYTES);

    precompute_kernel<<<NN + 1, DD>>>(X, W1, b1, W2, We, Wt);

    dim3 grid(NN / MT, NN);
    edge_main<<<grid, 256, SMEM_BYTES>>>(b2, be, bt, out);
}

// round 14
// speedup vs baseline: 2.3837x; 1.1266x over previous
#include <cuda_runtime.h>
#include <cuda_fp16.h>
#include <cstdint>

#define NN 2048
#define DD 64
#define MT 256

// ---------------- device scratch ----------------
__device__ __align__(16) unsigned short g_Ah[NN * DD];    // fp16 A rows
__device__ __align__(16) unsigned short g_Bh[NN * DD];    // fp16 B rows
__device__ __align__(16) unsigned short g_W2T[64 * 72];   // W2^T fp16, [n][k] pitch 72
__device__ __align__(16) unsigned short g_W3T[16 * 72];   // W3^T fp16

// ---------------- helpers ----------------
__device__ __forceinline__ uint32_t smem_u32(const void* p) {
    uint32_t a;
    asm("{ .reg .u64 t; cvta.to.shared.u64 t, %1; cvt.u32.u64 %0, t; }" : "=r"(a) : "l"(p));
    return a;
}
__device__ __forceinline__ uint32_t packf16(float hi, float lo) {
    uint32_t r; asm("cvt.rn.f16x2.f32 %0, %1, %2;" : "=r"(r) : "f"(hi), "f"(lo)); return r;
}
// relu(a+b) on packed fp16x2
__device__ __forceinline__ uint32_t haddrelu2(uint32_t a, uint32_t b) {
    const __half2 z = __half2half2(__ushort_as_half(0));
    __half2 r = __hmax2(__hadd2(*(__half2*)&a, *(__half2*)&b), z);
    return *(uint32_t*)&r;
}

#define LDSM_X4(r0, r1, r2, r3, addr) \
    asm volatile("ldmatrix.sync.aligned.m8n8.x4.shared.b16 {%0,%1,%2,%3}, [%4];" \
        : "=r"(r0), "=r"(r1), "=r"(r2), "=r"(r3) : "r"(addr))

__device__ __forceinline__ void mma_f16(float* c, uint32_t a0, uint32_t a1,
                                        uint32_t a2, uint32_t a3,
                                        uint32_t b0, uint32_t b1) {
    asm volatile(
        "mma.sync.aligned.m16n8k16.row.col.f32.f16.f16.f32 "
        "{%0,%1,%2,%3}, {%4,%5,%6,%7}, {%8,%9}, {%0,%1,%2,%3};"
        : "+f"(c[0]), "+f"(c[1]), "+f"(c[2]), "+f"(c[3])
        : "r"(a0), "r"(a1), "r"(a2), "r"(a3), "r"(b0), "r"(b1));
}

// ---------------- Kernel 1: precompute A/B rows + weight tiles ----------------
__global__ void precompute_kernel(const float* __restrict__ X,
                                  const float* __restrict__ W1,
                                  const float* __restrict__ b1,
                                  const float* __restrict__ W2,
                                  const float* __restrict__ We,
                                  const float* __restrict__ Wt) {
    if (blockIdx.x < NN) {
        __shared__ float xs[DD];
        const int i = blockIdx.x;
        const int d = threadIdx.x;
        xs[d] = X[i * DD + d];
        __syncthreads();
        float a = b1[d], b = 0.f;
#pragma unroll 8
        for (int k = 0; k < DD; k++) {
            const float xv = xs[k];
            a = fmaf(xv, __ldg(&W1[k * DD + d]), a);
            b = fmaf(xv, __ldg(&W1[(DD + k) * DD + d]), b);
        }
        g_Ah[i * DD + d] = __half_as_ushort(__float2half_rn(a));
        g_Bh[i * DD + d] = __half_as_ushort(__float2half_rn(b));
    } else {
        const int t = threadIdx.x;
        for (int idx = t; idx < 64 * 72; idx += 64) {
            const int n = idx / 72, k = idx % 72;
            float v = (k < 64) ? W2[k * 64 + n] : 0.f;
            g_W2T[idx] = __half_as_ushort(__float2half_rn(v));
        }
        for (int idx = t; idx < 16 * 72; idx += 64) {
            const int n = idx / 72, k = idx % 72;
            float v = 0.f;
            if (k < 64) {
                if (n == 0) v = We[k];
                else if (n < 9) v = Wt[k * 8 + n - 1];
            }
            g_W3T[idx] = __half_as_ushort(__float2half_rn(v));
        }
    }
}

// ---------------- SMEM layout (dynamic, 57920 B) ----------------
// sA   [256][72] fp16  @ 0       (36864)
// sB   [64][72]  fp16  @ 36864   (9216)
// sW3  [16][72]  fp16  @ 46080   (2304)
// sOut [256][9]  f32   @ 48384   (9216)
// sB2  [64]      f32   @ 57600   (256)
// sB3  [16]      f32   @ 57856   (64)
#define SMEM_BYTES 57920

// ---------------- Kernel 2: main pair kernel (fp16 1-pass, MT=256) ---------
__global__ __launch_bounds__(256, 2) void edge_main(
    const float* __restrict__ b2,
    const float* __restrict__ be, const float* __restrict__ bt,
    float* __restrict__ out)
{
    extern __shared__ __align__(16) char smem[];
    unsigned short* sA  = (unsigned short*)smem;
    unsigned short* sB  = (unsigned short*)(smem + 36864);
    unsigned short* sW3 = (unsigned short*)(smem + 46080);
    float* sOut = (float*)(smem + 48384);
    float* sB2  = (float*)(smem + 57600);
    float* sB3  = (float*)(smem + 57856);

    const int i  = blockIdx.y;
    const int jt = blockIdx.x;
    int jlo = jt * MT; if (i + 1 > jlo) jlo = i + 1;
    int jhi = jt * MT + MT; if (jhi > NN) jhi = NN;
    if (jlo >= jhi) return;
    const int cnt = jhi - jlo;

    const int tid  = threadIdx.x;
    const int warp = tid >> 5;
    const int lane = tid & 31;

    // ---- stage weights ----
    {
        const int4* srcB = (const int4*)g_W2T;
        int4* dstB = (int4*)sB;
        for (int idx = tid; idx < 576; idx += 256) dstB[idx] = srcB[idx];
        if (tid < 144) ((int4*)sW3)[tid] = ((const int4*)g_W3T)[tid];
        if (tid < 64) sB2[tid] = b2[tid];
        if (tid < 16) sB3[tid] = (tid == 0) ? be[0] : (tid < 9 ? bt[tid - 1] : 0.f);
    }

    // ---- stage h1 = relu(A[i]+B[j]) in fp16 (half2 math, 16B chunks) ----
    {
        const int4* gB = (const int4*)g_Bh;   // 8 halves per int4
        const int4* gA = (const int4*)g_Ah;
#pragma unroll
        for (int it = 0; it < 8; it++) {
            const int idx = tid + it * 256;
            const int m = idx >> 3, kc = idx & 7;
            const int j = jlo + m;
            int4 r = make_int4(0, 0, 0, 0);
            if (j < jhi) {
                const int4 bv = gB[j * 8 + kc];
                const int4 av = __ldg(&gA[i * 8 + kc]);
                r.x = (int)haddrelu2((uint32_t)av.x, (uint32_t)bv.x);
                r.y = (int)haddrelu2((uint32_t)av.y, (uint32_t)bv.y);
                r.z = (int)haddrelu2((uint32_t)av.z, (uint32_t)bv.z);
                r.w = (int)haddrelu2((uint32_t)av.w, (uint32_t)bv.w);
            }
            *(int4*)(sA + m * 72 + kc * 8) = r;
        }
    }
    __syncthreads();

    // ---- 1-pass fp16 GEMM, 2 m-tiles per warp (B frags shared) ----
    float acc[2][8][4];
#pragma unroll
    for (int mt = 0; mt < 2; mt++)
#pragma unroll
        for (int nt = 0; nt < 8; nt++)
#pragma unroll
            for (int c = 0; c < 4; c++) acc[mt][nt][c] = 0.f;

    const uint32_t ahbase = smem_u32(sA)
                          + (uint32_t)(warp * 32 + (lane & 15)) * 144 + (lane >> 4) * 16;
    // dual-nt B address: lanes 0-15 -> nt even rows, lanes 16-31 -> nt odd rows
    const uint32_t bbase = smem_u32(sB) + ((lane >= 16) ? 1152u : 0u)
                         + (uint32_t)(lane & 7) * 144 + ((lane >> 3) & 1) * 16;
    // dual-no W3 address: lanes 0-15 -> rows 0-7, lanes 16-31 -> rows 8-15
    const uint32_t w3base = smem_u32(sW3) + ((lane >= 16) ? 8u * 144u : 0u)
                          + (uint32_t)(lane & 7) * 144 + ((lane >> 3) & 1) * 16;

#pragma unroll
    for (int kt = 0; kt < 4; kt++) {
        uint32_t a[2][4];
        LDSM_X4(a[0][0], a[0][1], a[0][2], a[0][3], ahbase + kt * 32);
        LDSM_X4(a[1][0], a[1][1], a[1][2], a[1][3], ahbase + 2304 + kt * 32);
#pragma unroll
        for (int ntp = 0; ntp < 4; ntp++) {
            uint32_t b0, b1, b2v, b3v;
            LDSM_X4(b0, b1, b2v, b3v, bbase + (uint32_t)ntp * 2304 + kt * 32);
#pragma unroll
            for (int mt = 0; mt < 2; mt++) {
                mma_f16(acc[mt][2 * ntp],     a[mt][0], a[mt][1], a[mt][2], a[mt][3], b0, b1);
                mma_f16(acc[mt][2 * ntp + 1], a[mt][0], a[mt][1], a[mt][2], a[mt][3], b2v, b3v);
            }
        }
    }

    // ---- heads: relu+bias in regs, C->A fragment refeed, 1-pass vs W3 ----
    {
        const int tg = lane & 3;
#pragma unroll
        for (int mt = 0; mt < 2; mt++) {
            float oacc[2][4];
#pragma unroll
            for (int no = 0; no < 2; no++)
#pragma unroll
                for (int c = 0; c < 4; c++) oacc[no][c] = 0.f;

#pragma unroll
            for (int kt = 0; kt < 4; kt++) {
                const float2 bA = *(const float2*)(sB2 + (2 * kt) * 8 + tg * 2);
                const float2 bB = *(const float2*)(sB2 + (2 * kt + 1) * 8 + tg * 2);
                const float va0 = fmaxf(acc[mt][2 * kt][0] + bA.x, 0.f);
                const float va1 = fmaxf(acc[mt][2 * kt][1] + bA.y, 0.f);
                const float va2 = fmaxf(acc[mt][2 * kt][2] + bA.x, 0.f);
                const float va3 = fmaxf(acc[mt][2 * kt][3] + bA.y, 0.f);
                const float vb0 = fmaxf(acc[mt][2 * kt + 1][0] + bB.x, 0.f);
                const float vb1 = fmaxf(acc[mt][2 * kt + 1][1] + bB.y, 0.f);
                const float vb2 = fmaxf(acc[mt][2 * kt + 1][2] + bB.x, 0.f);
                const float vb3 = fmaxf(acc[mt][2 * kt + 1][3] + bB.y, 0.f);
                const uint32_t a0 = packf16(va1, va0);
                const uint32_t a1 = packf16(va3, va2);
                const uint32_t a2 = packf16(vb1, vb0);
                const uint32_t a3 = packf16(vb3, vb2);
                uint32_t w0, w1, w2, w3;
                LDSM_X4(w0, w1, w2, w3, w3base + kt * 32);
                mma_f16(oacc[0], a0, a1, a2, a3, w0, w1);
                mma_f16(oacc[1], a0, a1, a2, a3, w2, w3);
            }

            // store to sOut (pitch 9): cols 0-7 from tile 0, col 8 from tile 1
            const int r0 = warp * 32 + mt * 16 + (lane >> 2);
            const int r1 = r0 + 8;
            const int c0 = tg * 2;
            sOut[r0 * 9 + c0]     = oacc[0][0] + sB3[c0];
            sOut[r0 * 9 + c0 + 1] = oacc[0][1] + sB3[c0 + 1];
            sOut[r1 * 9 + c0]     = oacc[0][2] + sB3[c0];
            sOut[r1 * 9 + c0 + 1] = oacc[0][3] + sB3[c0 + 1];
            if (tg == 0) {
                sOut[r0 * 9 + 8] = oacc[1][0] + sB3[8];
                sOut[r1 * 9 + 8] = oacc[1][2] + sB3[8];
            }
        }
    }
    __syncthreads();

    // ---- packed-triu contiguous store ----
    const size_t pair0 = (size_t)i * (2 * NN - i - 1) / 2 + (size_t)(jlo - i - 1);
    float* gdst = out + pair0 * 9;
    const int tot = cnt * 9;
    for (int idx = tid; idx < tot; idx += 256) gdst[idx] = sOut[idx];
}

extern "C" void kernel_launch(void* const* d_in, const int* in_sizes, int n_in,
                              void* d_out, int out_size) {
    (void)in_sizes; (void)n_in; (void)out_size;
    const float* X  = (const float*)d_in[0];
    const float* W1 = (const float*)d_in[1];
    const float* b1 = (const float*)d_in[2];
    const float* W2 = (const float*)d_in[3];
    const float* b2 = (const float*)d_in[4];
    const float* We = (const float*)d_in[5];
    const float* be = (const float*)d_in[6];
    const float* Wt = (const float*)d_in[7];
    const float* bt = (const float*)d_in[8];
    float* out = (float*)d_out;

    cudaFuncSetAttribute(edge_main, cudaFuncAttributeMaxDynamicSharedMemorySize, SMEM_BYTES);

    precompute_kernel<<<NN + 1, DD>>>(X, W1, b1, W2, We, Wt);

    dim3 grid(NN / MT, NN);
    edge_main<<<grid, 256, SMEM_BYTES>>>(b2, be, bt, out);
}

// round 15
// speedup vs baseline: 2.6960x; 1.1310x over previous
#include <cuda_runtime.h>
#include <cuda_fp16.h>
#include <cstdint>

#define NN 2048
#define DD 64
#define MT 256

// ---------------- device scratch ----------------
__device__ __align__(16) unsigned short g_Ah[NN * DD];    // fp16 A rows
__device__ __align__(16) unsigned short g_Bh[NN * DD];    // fp16 B rows
__device__ __align__(16) unsigned short g_W2T[64 * 72];   // W2^T fp16, [n][k] pitch 72
__device__ __align__(16) unsigned short g_W3T[16 * 72];   // W3^T fp16

// ---------------- helpers ----------------
__device__ __forceinline__ uint32_t smem_u32(const void* p) {
    uint32_t a;
    asm("{ .reg .u64 t; cvta.to.shared.u64 t, %1; cvt.u32.u64 %0, t; }" : "=r"(a) : "l"(p));
    return a;
}
__device__ __forceinline__ uint32_t packf16(float hi, float lo) {
    uint32_t r; asm("cvt.rn.f16x2.f32 %0, %1, %2;" : "=r"(r) : "f"(hi), "f"(lo)); return r;
}
// relu(a+b) on packed fp16x2
__device__ __forceinline__ uint32_t haddrelu2(uint32_t a, uint32_t b) {
    const __half2 z = __half2half2(__ushort_as_half(0));
    __half2 r = __hmax2(__hadd2(*(__half2*)&a, *(__half2*)&b), z);
    return *(uint32_t*)&r;
}

#define LDSM_X4(r0, r1, r2, r3, addr) \
    asm volatile("ldmatrix.sync.aligned.m8n8.x4.shared.b16 {%0,%1,%2,%3}, [%4];" \
        : "=r"(r0), "=r"(r1), "=r"(r2), "=r"(r3) : "r"(addr))

__device__ __forceinline__ void mma_f16(float* c, uint32_t a0, uint32_t a1,
                                        uint32_t a2, uint32_t a3,
                                        uint32_t b0, uint32_t b1) {
    asm volatile(
        "mma.sync.aligned.m16n8k16.row.col.f32.f16.f16.f32 "
        "{%0,%1,%2,%3}, {%4,%5,%6,%7}, {%8,%9}, {%0,%1,%2,%3};"
        : "+f"(c[0]), "+f"(c[1]), "+f"(c[2]), "+f"(c[3])
        : "r"(a0), "r"(a1), "r"(a2), "r"(a3), "r"(b0), "r"(b1));
}

// ---------------- Kernel 1: precompute A/B rows + weight tiles ----------------
__global__ void precompute_kernel(const float* __restrict__ X,
                                  const float* __restrict__ W1,
                                  const float* __restrict__ b1,
                                  const float* __restrict__ W2,
                                  const float* __restrict__ We,
                                  const float* __restrict__ Wt) {
    if (blockIdx.x < NN) {
        __shared__ float xs[DD];
        const int i = blockIdx.x;
        const int d = threadIdx.x;
        xs[d] = X[i * DD + d];
        __syncthreads();
        float a = b1[d], b = 0.f;
#pragma unroll 8
        for (int k = 0; k < DD; k++) {
            const float xv = xs[k];
            a = fmaf(xv, __ldg(&W1[k * DD + d]), a);
            b = fmaf(xv, __ldg(&W1[(DD + k) * DD + d]), b);
        }
        g_Ah[i * DD + d] = __half_as_ushort(__float2half_rn(a));
        g_Bh[i * DD + d] = __half_as_ushort(__float2half_rn(b));
    } else {
        const int t = threadIdx.x;
        for (int idx = t; idx < 64 * 72; idx += 64) {
            const int n = idx / 72, k = idx % 72;
            float v = (k < 64) ? W2[k * 64 + n] : 0.f;
            g_W2T[idx] = __half_as_ushort(__float2half_rn(v));
        }
        for (int idx = t; idx < 16 * 72; idx += 64) {
            const int n = idx / 72, k = idx % 72;
            float v = 0.f;
            if (k < 64) {
                if (n == 0) v = We[k];
                else if (n < 9) v = Wt[k * 8 + n - 1];
            }
            g_W3T[idx] = __half_as_ushort(__float2half_rn(v));
        }
    }
}

// ---------------- SMEM layout (dynamic, 48704 B) ----------------
// sA   [256][72] fp16  @ 0       (36864)
// sB   [64][72]  fp16  @ 36864   (9216)
// sW3  [16][72]  fp16  @ 46080   (2304)
// sB2  [64]      f32   @ 48384   (256)
// sB3  [16]      f32   @ 48640   (64)
#define SMEM_BYTES 48704

// ---------------- Kernel 2: main pair kernel (fp16 1-pass, MT=256) ---------
__global__ __launch_bounds__(256, 2) void edge_main(
    const float* __restrict__ b2,
    const float* __restrict__ be, const float* __restrict__ bt,
    float* __restrict__ out)
{
    extern __shared__ __align__(16) char smem[];
    unsigned short* sA  = (unsigned short*)smem;
    unsigned short* sB  = (unsigned short*)(smem + 36864);
    unsigned short* sW3 = (unsigned short*)(smem + 46080);
    float* sB2  = (float*)(smem + 48384);
    float* sB3  = (float*)(smem + 48640);

    const int i  = blockIdx.y;
    const int jt = blockIdx.x;
    int jlo = jt * MT; if (i + 1 > jlo) jlo = i + 1;
    int jhi = jt * MT + MT; if (jhi > NN) jhi = NN;
    if (jlo >= jhi) return;
    const int cnt = jhi - jlo;

    const int tid  = threadIdx.x;
    const int warp = tid >> 5;
    const int lane = tid & 31;

    // ---- stage weights ----
    {
        const int4* srcB = (const int4*)g_W2T;
        int4* dstB = (int4*)sB;
        for (int idx = tid; idx < 576; idx += 256) dstB[idx] = srcB[idx];
        if (tid < 144) ((int4*)sW3)[tid] = ((const int4*)g_W3T)[tid];
        if (tid < 64) sB2[tid] = b2[tid];
        if (tid < 16) sB3[tid] = (tid == 0) ? be[0] : (tid < 9 ? bt[tid - 1] : 0.f);
    }

    // ---- stage h1 = relu(A[i]+B[j]) in fp16 (half2 math, 16B chunks) ----
    {
        const int4* gB = (const int4*)g_Bh;   // 8 halves per int4
        const int4* gA = (const int4*)g_Ah;
#pragma unroll
        for (int it = 0; it < 8; it++) {
            const int idx = tid + it * 256;
            const int m = idx >> 3, kc = idx & 7;
            const int j = jlo + m;
            int4 r = make_int4(0, 0, 0, 0);
            if (j < jhi) {
                const int4 bv = gB[j * 8 + kc];
                const int4 av = __ldg(&gA[i * 8 + kc]);
                r.x = (int)haddrelu2((uint32_t)av.x, (uint32_t)bv.x);
                r.y = (int)haddrelu2((uint32_t)av.y, (uint32_t)bv.y);
                r.z = (int)haddrelu2((uint32_t)av.z, (uint32_t)bv.z);
                r.w = (int)haddrelu2((uint32_t)av.w, (uint32_t)bv.w);
            }
            *(int4*)(sA + m * 72 + kc * 8) = r;
        }
    }
    __syncthreads();

    // ---- 1-pass fp16 GEMM, 2 m-tiles per warp (B frags shared) ----
    float acc[2][8][4];
#pragma unroll
    for (int mt = 0; mt < 2; mt++)
#pragma unroll
        for (int nt = 0; nt < 8; nt++)
#pragma unroll
            for (int c = 0; c < 4; c++) acc[mt][nt][c] = 0.f;

    const uint32_t ahbase = smem_u32(sA)
                          + (uint32_t)(warp * 32 + (lane & 15)) * 144 + (lane >> 4) * 16;
    // dual-nt B address: lanes 0-15 -> nt even rows, lanes 16-31 -> nt odd rows
    const uint32_t bbase = smem_u32(sB) + ((lane >= 16) ? 1152u : 0u)
                         + (uint32_t)(lane & 7) * 144 + ((lane >> 3) & 1) * 16;
    // dual-no W3 address: lanes 0-15 -> rows 0-7, lanes 16-31 -> rows 8-15
    const uint32_t w3base = smem_u32(sW3) + ((lane >= 16) ? 8u * 144u : 0u)
                          + (uint32_t)(lane & 7) * 144 + ((lane >> 3) & 1) * 16;

#pragma unroll
    for (int kt = 0; kt < 4; kt++) {
        uint32_t a[2][4];
        LDSM_X4(a[0][0], a[0][1], a[0][2], a[0][3], ahbase + kt * 32);
        LDSM_X4(a[1][0], a[1][1], a[1][2], a[1][3], ahbase + 2304 + kt * 32);
#pragma unroll
        for (int ntp = 0; ntp < 4; ntp++) {
            uint32_t b0, b1, b2v, b3v;
            LDSM_X4(b0, b1, b2v, b3v, bbase + (uint32_t)ntp * 2304 + kt * 32);
#pragma unroll
            for (int mt = 0; mt < 2; mt++) {
                mma_f16(acc[mt][2 * ntp],     a[mt][0], a[mt][1], a[mt][2], a[mt][3], b0, b1);
                mma_f16(acc[mt][2 * ntp + 1], a[mt][0], a[mt][1], a[mt][2], a[mt][3], b2v, b3v);
            }
        }
    }

    // ---- heads: W3 frags hoisted to regs (tile-invariant), direct STG out ----
    {
        const int tg = lane & 3;
        uint32_t w[4][4];
#pragma unroll
        for (int kt = 0; kt < 4; kt++)
            LDSM_X4(w[kt][0], w[kt][1], w[kt][2], w[kt][3], w3base + kt * 32);

        const size_t pair0 = (size_t)i * (2 * NN - i - 1) / 2 + (size_t)(jlo - i - 1);
        const int c0 = tg * 2;
        const float hb0 = sB3[c0], hb1 = sB3[c0 + 1], hb8 = sB3[8];

#pragma unroll
        for (int mt = 0; mt < 2; mt++) {
            float oacc[2][4];
#pragma unroll
            for (int no = 0; no < 2; no++)
#pragma unroll
                for (int c = 0; c < 4; c++) oacc[no][c] = 0.f;

#pragma unroll
            for (int kt = 0; kt < 4; kt++) {
                const float2 bA = *(const float2*)(sB2 + (2 * kt) * 8 + tg * 2);
                const float2 bB = *(const float2*)(sB2 + (2 * kt + 1) * 8 + tg * 2);
                const float va0 = fmaxf(acc[mt][2 * kt][0] + bA.x, 0.f);
                const float va1 = fmaxf(acc[mt][2 * kt][1] + bA.y, 0.f);
                const float va2 = fmaxf(acc[mt][2 * kt][2] + bA.x, 0.f);
                const float va3 = fmaxf(acc[mt][2 * kt][3] + bA.y, 0.f);
                const float vb0 = fmaxf(acc[mt][2 * kt + 1][0] + bB.x, 0.f);
                const float vb1 = fmaxf(acc[mt][2 * kt + 1][1] + bB.y, 0.f);
                const float vb2 = fmaxf(acc[mt][2 * kt + 1][2] + bB.x, 0.f);
                const float vb3 = fmaxf(acc[mt][2 * kt + 1][3] + bB.y, 0.f);
                const uint32_t a0 = packf16(va1, va0);
                const uint32_t a1 = packf16(va3, va2);
                const uint32_t a2 = packf16(vb1, vb0);
                const uint32_t a3 = packf16(vb3, vb2);
                mma_f16(oacc[0], a0, a1, a2, a3, w[kt][0], w[kt][1]);
                mma_f16(oacc[1], a0, a1, a2, a3, w[kt][2], w[kt][3]);
            }

            // direct packed-triu store: cols 0-7 from tile 0, col 8 from tile 1
            const int r0 = warp * 32 + mt * 16 + (lane >> 2);
            const int r1 = r0 + 8;
            if (r0 < cnt) {
                float* d = out + (pair0 + r0) * 9;
                d[c0]     = oacc[0][0] + hb0;
                d[c0 + 1] = oacc[0][1] + hb1;
                if (tg == 0) d[8] = oacc[1][0] + hb8;
            }
            if (r1 < cnt) {
                float* d = out + (pair0 + r1) * 9;
                d[c0]     = oacc[0][2] + hb0;
                d[c0 + 1] = oacc[0][3] + hb1;
                if (tg == 0) d[8] = oacc[1][2] + hb8;
            }
        }
    }
}

extern "C" void kernel_launch(void* const* d_in, const int* in_sizes, int n_in,
                              void* d_out, int out_size) {
    (void)in_sizes; (void)n_in; (void)out_size;
    const float* X  = (const float*)d_in[0];
    const float* W1 = (const float*)d_in[1];
    const float* b1 = (const float*)d_in[2];
    const float* W2 = (const float*)d_in[3];
    const float* b2 = (const float*)d_in[4];
    const float* We = (const float*)d_in[5];
    const float* be = (const float*)d_in[6];
    const float* Wt = (const float*)d_in[7];
    const float* bt = (const float*)d_in[8];
    float* out = (float*)d_out;

    cudaFuncSetAttribute(edge_main, cudaFuncAttributeMaxDynamicSharedMemorySize, SMEM_BYTES);

    precompute_kernel<<<NN + 1, DD>>>(X, W1, b1, W2, We, Wt);

    dim3 grid(NN / MT, NN);
    edge_main<<<grid, 256, SMEM_BYTES>>>(b2, be, bt, out);
}

// round 16
// speedup vs baseline: 3.5873x; 1.3306x over previous
#include <cuda_runtime.h>
#include <cuda_fp16.h>
#include <cstdint>

#define NN 2048
#define DD 64
#define MT 256
#define IB 4

// ---------------- device scratch ----------------
__device__ __align__(16) unsigned short g_Ah[NN * DD];    // fp16 A rows
__device__ __align__(16) unsigned short g_Bh[NN * DD];    // fp16 B rows
__device__ __align__(16) unsigned short g_W2T[64 * 72];   // W2^T fp16, [n][k] pitch 72
__device__ __align__(16) unsigned short g_W3T[16 * 72];   // W3^T fp16

// ---------------- helpers ----------------
__device__ __forceinline__ uint32_t smem_u32(const void* p) {
    uint32_t a;
    asm("{ .reg .u64 t; cvta.to.shared.u64 t, %1; cvt.u32.u64 %0, t; }" : "=r"(a) : "l"(p));
    return a;
}
__device__ __forceinline__ uint32_t packf16(float hi, float lo) {
    uint32_t r; asm("cvt.rn.f16x2.f32 %0, %1, %2;" : "=r"(r) : "f"(hi), "f"(lo)); return r;
}
// relu(a+b) on packed fp16x2
__device__ __forceinline__ uint32_t haddrelu2(uint32_t a, uint32_t b) {
    const __half2 z = __half2half2(__ushort_as_half(0));
    __half2 r = __hmax2(__hadd2(*(__half2*)&a, *(__half2*)&b), z);
    return *(uint32_t*)&r;
}

#define CP_ASYNC16(dst, src) \
    asm volatile("cp.async.cg.shared.global [%0], [%1], 16;" :: "r"(dst), "l"(src))
#define CP_ASYNC_COMMIT() asm volatile("cp.async.commit_group;" ::: "memory")
#define CP_ASYNC_WAIT0()  asm volatile("cp.async.wait_group 0;" ::: "memory")

#define LDSM_X4(r0, r1, r2, r3, addr) \
    asm volatile("ldmatrix.sync.aligned.m8n8.x4.shared.b16 {%0,%1,%2,%3}, [%4];" \
        : "=r"(r0), "=r"(r1), "=r"(r2), "=r"(r3) : "r"(addr))

__device__ __forceinline__ void mma_f16(float* c, uint32_t a0, uint32_t a1,
                                        uint32_t a2, uint32_t a3,
                                        uint32_t b0, uint32_t b1) {
    asm volatile(
        "mma.sync.aligned.m16n8k16.row.col.f32.f16.f16.f32 "
        "{%0,%1,%2,%3}, {%4,%5,%6,%7}, {%8,%9}, {%0,%1,%2,%3};"
        : "+f"(c[0]), "+f"(c[1]), "+f"(c[2]), "+f"(c[3])
        : "r"(a0), "r"(a1), "r"(a2), "r"(a3), "r"(b0), "r"(b1));
}

// ---------------- Kernel 1: precompute A/B rows + weight tiles ----------------
__global__ void precompute_kernel(const float* __restrict__ X,
                                  const float* __restrict__ W1,
                                  const float* __restrict__ b1,
                                  const float* __restrict__ W2,
                                  const float* __restrict__ We,
                                  const float* __restrict__ Wt) {
    if (blockIdx.x < NN) {
        __shared__ float xs[DD];
        const int i = blockIdx.x;
        const int d = threadIdx.x;
        xs[d] = X[i * DD + d];
        __syncthreads();
        float a = b1[d], b = 0.f;
#pragma unroll 8
        for (int k = 0; k < DD; k++) {
            const float xv = xs[k];
            a = fmaf(xv, __ldg(&W1[k * DD + d]), a);
            b = fmaf(xv, __ldg(&W1[(DD + k) * DD + d]), b);
        }
        g_Ah[i * DD + d] = __half_as_ushort(__float2half_rn(a));
        g_Bh[i * DD + d] = __half_as_ushort(__float2half_rn(b));
    } else {
        const int t = threadIdx.x;
        for (int idx = t; idx < 64 * 72; idx += 64) {
            const int n = idx / 72, k = idx % 72;
            float v = (k < 64) ? W2[k * 64 + n] : 0.f;
            g_W2T[idx] = __half_as_ushort(__float2half_rn(v));
        }
        for (int idx = t; idx < 16 * 72; idx += 64) {
            const int n = idx / 72, k = idx % 72;
            float v = 0.f;
            if (k < 64) {
                if (n == 0) v = We[k];
                else if (n < 9) v = Wt[k * 8 + n - 1];
            }
            g_W3T[idx] = __half_as_ushort(__float2half_rn(v));
        }
    }
}

// ---------------- SMEM layout (dynamic, 49728 B) ----------------
// sRB  [256][72] fp16  @ 0       (36864)   raw B rows (i-independent!)
// sB   [64][72]  fp16  @ 36864   (9216)    W2^T
// sW3  [16][72]  fp16  @ 46080   (2304)
// sAi  [IB][64]  fp16  @ 48384   (512)     A rows for the i-batch
// sB2  [64]      f32   @ 48896   (256)
// sB3  [16]      f32   @ 49152   (64)
#define SMEM_BYTES 49728

// ---------------- Kernel 2: i-batched pair kernel ----------------
// Block covers i in [i0, i0+IB) x j in [j0, j0+MT). Raw B rows staged ONCE
// (pure cp.async copy); per-i h1 is built at fragment level by folding the
// 8 per-lane A columns into the ldmatrix'd raw-B fragments (hadd2+hmax2).
__global__ __launch_bounds__(256, 2) void edge_main(
    const float* __restrict__ b2,
    const float* __restrict__ be, const float* __restrict__ bt,
    float* __restrict__ out)
{
    extern __shared__ __align__(16) char smem[];
    unsigned short* sRB = (unsigned short*)smem;
    unsigned short* sB  = (unsigned short*)(smem + 36864);
    unsigned short* sW3 = (unsigned short*)(smem + 46080);
    unsigned short* sAi = (unsigned short*)(smem + 48384);
    float* sB2 = (float*)(smem + 48896);
    float* sB3 = (float*)(smem + 49152);

    const int jt = blockIdx.x;
    const int it = blockIdx.y;
    const int j0 = jt * MT;
    const int i0 = it * IB;
    if (j0 + MT - 1 <= i0) return;   // no j > i anywhere in this block

    const int tid  = threadIdx.x;
    const int warp = tid >> 5;
    const int lane = tid & 31;

    // ---- stage raw B rows (cp.async, pure copy) + weights + A rows ----
    {
        const uint32_t rbbase = smem_u32(sRB);
#pragma unroll
        for (int c = 0; c < 8; c++) {
            const int idx = tid + c * 256;
            const int m = idx >> 3, kc = idx & 7;
            CP_ASYNC16(rbbase + (uint32_t)(m * 72 + kc * 8) * 2,
                       (const char*)(g_Bh + (size_t)(j0 + m) * 64 + kc * 8));
        }
        CP_ASYNC_COMMIT();

        const int4* srcB = (const int4*)g_W2T;
        int4* dstB = (int4*)sB;
        for (int idx = tid; idx < 576; idx += 256) dstB[idx] = srcB[idx];
        if (tid < 144) ((int4*)sW3)[tid] = ((const int4*)g_W3T)[tid];
        if (tid < 32) ((int4*)sAi)[tid] = ((const int4*)(g_Ah + (size_t)i0 * 64))[tid];
        if (tid < 64) sB2[tid] = b2[tid];
        if (tid < 16) sB3[tid] = (tid == 0) ? be[0] : (tid < 9 ? bt[tid - 1] : 0.f);
        CP_ASYNC_WAIT0();
    }
    __syncthreads();

    const int g  = lane >> 2;
    const int t2 = (lane & 3) * 2;
    const int tg = lane & 3;

    const uint32_t rbfrag = smem_u32(sRB)
                          + (uint32_t)(warp * 32 + (lane & 15)) * 144 + (lane >> 4) * 16;
    // dual-nt B address: lanes 0-15 -> nt even rows, lanes 16-31 -> nt odd rows
    const uint32_t bbase = smem_u32(sB) + ((lane >= 16) ? 1152u : 0u)
                         + (uint32_t)(lane & 7) * 144 + ((lane >> 3) & 1) * 16;
    // dual-no W3 address: lanes 0-15 -> rows 0-7, lanes 16-31 -> rows 8-15
    const uint32_t w3base = smem_u32(sW3) + ((lane >= 16) ? 8u * 144u : 0u)
                          + (uint32_t)(lane & 7) * 144 + ((lane >> 3) & 1) * 16;

    // tile-invariant W3 fragments (registers)
    uint32_t w[4][4];
#pragma unroll
    for (int kt = 0; kt < 4; kt++)
        LDSM_X4(w[kt][0], w[kt][1], w[kt][2], w[kt][3], w3base + kt * 32);

    const int c0 = tg * 2;
    const float hb0 = sB3[c0], hb1 = sB3[c0 + 1], hb8 = sB3[8];

    // ---- i-batch loop (smem is read-only inside; no syncs) ----
#pragma unroll 1
    for (int ii = 0; ii < IB; ii++) {
        const int i = i0 + ii;
        if (i >= j0 + MT - 1) continue;   // no valid j for this i

        // per-lane A columns for this i (8 half2 regs)
        uint32_t aA[4][2];
#pragma unroll
        for (int kt = 0; kt < 4; kt++) {
            aA[kt][0] = *(const uint32_t*)(sAi + ii * 64 + kt * 16 + t2);
            aA[kt][1] = *(const uint32_t*)(sAi + ii * 64 + kt * 16 + t2 + 8);
        }

        float acc[2][8][4];
#pragma unroll
        for (int mt = 0; mt < 2; mt++)
#pragma unroll
            for (int nt = 0; nt < 8; nt++)
#pragma unroll
                for (int c = 0; c < 4; c++) acc[mt][nt][c] = 0.f;

#pragma unroll
        for (int kt = 0; kt < 4; kt++) {
            uint32_t a[2][4];
            LDSM_X4(a[0][0], a[0][1], a[0][2], a[0][3], rbfrag + kt * 32);
            LDSM_X4(a[1][0], a[1][1], a[1][2], a[1][3], rbfrag + 2304 + kt * 32);
            // fold A[i] + relu at fragment level
#pragma unroll
            for (int mt = 0; mt < 2; mt++) {
                a[mt][0] = haddrelu2(a[mt][0], aA[kt][0]);
                a[mt][1] = haddrelu2(a[mt][1], aA[kt][0]);
                a[mt][2] = haddrelu2(a[mt][2], aA[kt][1]);
                a[mt][3] = haddrelu2(a[mt][3], aA[kt][1]);
            }
#pragma unroll
            for (int ntp = 0; ntp < 4; ntp++) {
                uint32_t b0, b1, b2v, b3v;
                LDSM_X4(b0, b1, b2v, b3v, bbase + (uint32_t)ntp * 2304 + kt * 32);
#pragma unroll
                for (int mt = 0; mt < 2; mt++) {
                    mma_f16(acc[mt][2 * ntp],     a[mt][0], a[mt][1], a[mt][2], a[mt][3], b0, b1);
                    mma_f16(acc[mt][2 * ntp + 1], a[mt][0], a[mt][1], a[mt][2], a[mt][3], b2v, b3v);
                }
            }
        }

        // ---- heads + direct packed-triu store ----
        const size_t tb = (size_t)i * (2 * NN - i - 1) / 2;
#pragma unroll
        for (int mt = 0; mt < 2; mt++) {
            float oacc[2][4];
#pragma unroll
            for (int no = 0; no < 2; no++)
#pragma unroll
                for (int c = 0; c < 4; c++) oacc[no][c] = 0.f;

#pragma unroll
            for (int kt = 0; kt < 4; kt++) {
                const float2 bA = *(const float2*)(sB2 + (2 * kt) * 8 + tg * 2);
                const float2 bB = *(const float2*)(sB2 + (2 * kt + 1) * 8 + tg * 2);
                const float va0 = fmaxf(acc[mt][2 * kt][0] + bA.x, 0.f);
                const float va1 = fmaxf(acc[mt][2 * kt][1] + bA.y, 0.f);
                const float va2 = fmaxf(acc[mt][2 * kt][2] + bA.x, 0.f);
                const float va3 = fmaxf(acc[mt][2 * kt][3] + bA.y, 0.f);
                const float vb0 = fmaxf(acc[mt][2 * kt + 1][0] + bB.x, 0.f);
                const float vb1 = fmaxf(acc[mt][2 * kt + 1][1] + bB.y, 0.f);
                const float vb2 = fmaxf(acc[mt][2 * kt + 1][2] + bB.x, 0.f);
                const float vb3 = fmaxf(acc[mt][2 * kt + 1][3] + bB.y, 0.f);
                const uint32_t a0 = packf16(va1, va0);
                const uint32_t a1 = packf16(va3, va2);
                const uint32_t a2 = packf16(vb1, vb0);
                const uint32_t a3 = packf16(vb3, vb2);
                mma_f16(oacc[0], a0, a1, a2, a3, w[kt][0], w[kt][1]);
                mma_f16(oacc[1], a0, a1, a2, a3, w[kt][2], w[kt][3]);
            }

            const int r0 = warp * 32 + mt * 16 + g;
            const int r1 = r0 + 8;
            const int jr0 = j0 + r0, jr1 = j0 + r1;
            if (jr0 > i) {
                float* d = out + (tb + (size_t)(jr0 - i - 1)) * 9;
                d[c0]     = oacc[0][0] + hb0;
                d[c0 + 1] = oacc[0][1] + hb1;
                if (tg == 0) d[8] = oacc[1][0] + hb8;
            }
            if (jr1 > i) {
                float* d = out + (tb + (size_t)(jr1 - i - 1)) * 9;
                d[c0]     = oacc[0][2] + hb0;
                d[c0 + 1] = oacc[0][3] + hb1;
                if (tg == 0) d[8] = oacc[1][2] + hb8;
            }
        }
    }
}

extern "C" void kernel_launch(void* const* d_in, const int* in_sizes, int n_in,
                              void* d_out, int out_size) {
    (void)in_sizes; (void)n_in; (void)out_size;
    const float* X  = (const float*)d_in[0];
    const float* W1 = (const float*)d_in[1];
    const float* b1 = (const float*)d_in[2];
    const float* W2 = (const float*)d_in[3];
    const float* b2 = (const float*)d_in[4];
    const float* We = (const float*)d_in[5];
    const float* be = (const float*)d_in[6];
    const float* Wt = (const float*)d_in[7];
    const float* bt = (const float*)d_in[8];
    float* out = (float*)d_out;

    cudaFuncSetAttribute(edge_main, cudaFuncAttributeMaxDynamicSharedMemorySize, SMEM_BYTES);

    precompute_kernel<<<NN + 1, DD>>>(X, W1, b1, W2, We, Wt);

    dim3 grid(NN / MT, NN / IB);
    edge_main<<<grid, 256, SMEM_BYTES>>>(b2, be, bt, out);
}